// round 1
// baseline (speedup 1.0000x reference)
#include <cuda_runtime.h>

// Problem constants: (b=4, n=8, d=64, s=8192) fp32
#define DD 64
#define SS 8192
#define NHEADS 32            // b * n_heads
#define NC 16                // split-K chunks over s for context GEMM
#define CHUNK (SS / NC)      // 512
#define TSZ 32               // s-tile inside a chunk
#define PADW 68              // smem row pad (keeps 16B alignment, low conflicts)

// Scratch (no allocations allowed): partial context, partial Z, final scaled context
__device__ float g_Upart[NHEADS * NC * DD * DD];  // 8 MB
__device__ float g_Zpart[NHEADS * NC * DD];
__device__ float g_C[NHEADS * DD * DD];           // C[i][j] * scale / Z_i

// ---- Blackwell packed fp32 pair math (2x FFMA rate; PTX-only) ----
__device__ __forceinline__ void fma2(unsigned long long &d, unsigned long long a, unsigned long long b) {
    asm("fma.rn.f32x2 %0, %1, %2, %0;" : "+l"(d) : "l"(a), "l"(b));
}
__device__ __forceinline__ unsigned long long dup2(float x) {
    unsigned long long r;
    asm("mov.b64 %0, {%1, %1};" : "=l"(r) : "f"(x));
    return r;
}
__device__ __forceinline__ float2 unpack2(unsigned long long v) {
    float2 f;
    asm("mov.b64 {%0, %1}, %2;" : "=f"(f.x), "=f"(f.y) : "l"(v));
    return f;
}

// ============================================================================
// Kernel B: per (head, chunk): U_part[i][j] = sum_s exp(k[i,s]) * v[j,s]
//                              Z_part[i]    = sum_s exp(k[i,s])
// 64 threads, each computes an 8x8 output tile (as 4 i-pairs x 8 j in f32x2).
// ============================================================================
__global__ __launch_bounds__(64) void kB(const float* __restrict__ K,
                                         const float* __restrict__ V) {
    __shared__ __align__(16) float Kt[TSZ][PADW];  // [s-in-tile][i] (exp applied)
    __shared__ __align__(16) float Vt[TSZ][PADW];  // [s-in-tile][j]

    const int h = blockIdx.y;
    const int c = blockIdx.x;
    const float* kh = K + (size_t)h * DD * SS + c * CHUNK;
    const float* vh = V + (size_t)h * DD * SS + c * CHUNK;

    const int tid = threadIdx.x;
    const int ti = tid & 7;   // i-group: rows 8*ti .. 8*ti+7
    const int tj = tid >> 3;  // j-group: cols 8*tj .. 8*tj+7
    const int lrow = tid >> 3;  // loader: base row
    const int lc4  = tid & 7;   // loader: float4 slot within 32-float tile row

    unsigned long long acc[4][8];  // [i-pair][j]
    #pragma unroll
    for (int m = 0; m < 4; m++)
        #pragma unroll
        for (int j = 0; j < 8; j++) acc[m][j] = 0ull;

    float zacc[8];
    #pragma unroll
    for (int e = 0; e < 8; e++) zacc[e] = 0.f;

    for (int tt = 0; tt < CHUNK / TSZ; ++tt) {
        const int s0 = tt * TSZ;
        __syncthreads();
        // Load + exp + transpose K, transpose V. 8 float4 per thread per array.
        #pragma unroll
        for (int e = 0; e < 8; ++e) {
            const int row = lrow + 8 * e;
            const float4 k4 = *(const float4*)(kh + (size_t)row * SS + s0 + lc4 * 4);
            const float e0 = __expf(k4.x), e1 = __expf(k4.y),
                        e2 = __expf(k4.z), e3 = __expf(k4.w);
            Kt[lc4 * 4 + 0][row] = e0;
            Kt[lc4 * 4 + 1][row] = e1;
            Kt[lc4 * 4 + 2][row] = e2;
            Kt[lc4 * 4 + 3][row] = e3;
            zacc[e] += (e0 + e1) + (e2 + e3);
            const float4 v4 = *(const float4*)(vh + (size_t)row * SS + s0 + lc4 * 4);
            Vt[lc4 * 4 + 0][row] = v4.x;
            Vt[lc4 * 4 + 1][row] = v4.y;
            Vt[lc4 * 4 + 2][row] = v4.z;
            Vt[lc4 * 4 + 3][row] = v4.w;
        }
        __syncthreads();
        // 64x64 x TSZ outer-product accumulation, packed pairs along i.
        #pragma unroll 8
        for (int t = 0; t < TSZ; ++t) {
            unsigned long long a[4];
            #pragma unroll
            for (int m = 0; m < 4; m++)
                a[m] = *(const unsigned long long*)&Kt[t][8 * ti + 2 * m];
            #pragma unroll
            for (int j = 0; j < 8; j++) {
                const unsigned long long bb = dup2(Vt[t][8 * tj + j]);
                #pragma unroll
                for (int m = 0; m < 4; m++) fma2(acc[m][j], a[m], bb);
            }
        }
    }

    // Store partial U (no atomics; reduced by kB2).
    float* up = g_Upart + (size_t)(h * NC + c) * DD * DD;
    #pragma unroll
    for (int m = 0; m < 4; m++) {
        float r0[8], r1[8];
        #pragma unroll
        for (int j = 0; j < 8; j++) {
            const float2 f = unpack2(acc[m][j]);
            r0[j] = f.x;
            r1[j] = f.y;
        }
        const int i0 = 8 * ti + 2 * m;
        *(float4*)(up + i0 * DD + 8 * tj)           = make_float4(r0[0], r0[1], r0[2], r0[3]);
        *(float4*)(up + i0 * DD + 8 * tj + 4)       = make_float4(r0[4], r0[5], r0[6], r0[7]);
        *(float4*)(up + (i0 + 1) * DD + 8 * tj)     = make_float4(r1[0], r1[1], r1[2], r1[3]);
        *(float4*)(up + (i0 + 1) * DD + 8 * tj + 4) = make_float4(r1[4], r1[5], r1[6], r1[7]);
    }

    // Z partial: reduce across the 8 lanes sharing a row (lc4 = 0..7).
    #pragma unroll
    for (int e = 0; e < 8; e++) {
        float z = zacc[e];
        z += __shfl_down_sync(0xffffffffu, z, 4, 8);
        z += __shfl_down_sync(0xffffffffu, z, 2, 8);
        z += __shfl_down_sync(0xffffffffu, z, 1, 8);
        if (lc4 == 0) g_Zpart[(h * NC + c) * DD + lrow + 8 * e] = z;
    }
}

// ============================================================================
// Kernel B2: reduce NC partials -> g_C[i][j] = scale * U[i][j] / Z[i]
// ============================================================================
__global__ void kB2() {
    const int idx = blockIdx.x * 256 + threadIdx.x;
    if (idx >= NHEADS * DD * DD) return;
    const int h = idx >> 12;       // / 4096
    const int ij = idx & 4095;
    const int i = ij >> 6;
    float u = 0.f;
    #pragma unroll
    for (int c = 0; c < NC; c++) u += g_Upart[((size_t)(h * NC + c) << 12) + ij];
    float z = 0.f;
    #pragma unroll
    for (int c = 0; c < NC; c++) z += g_Zpart[(h * NC + c) * DD + i];
    g_C[idx] = u * (0.125f / z);   // scale = 64^-0.5 = 0.125
}

// ============================================================================
// Kernel C: per (head, 64-wide s-tile):
//   qe[i][s] = exp(q[i][s]); rinv[s] = 1/sum_i qe
//   out[j][s] = rinv[s] * sum_i g_C[i][j] * qe[i][s]
// 64 threads, 8j x 8s register tile (s-pairs packed for f32x2).
// ============================================================================
__global__ __launch_bounds__(64) void kC(const float* __restrict__ Q,
                                         float* __restrict__ O) {
    __shared__ __align__(16) float Cs[DD][PADW];
    __shared__ __align__(16) float Qs[DD][PADW];
    __shared__ float rs[64];

    const int h = blockIdx.y;
    const int s0 = blockIdx.x * 64;
    const float* qh = Q + (size_t)h * DD * SS + s0;
    float* oh = O + (size_t)h * DD * SS + s0;
    const int tid = threadIdx.x;

    // Load C (already normalized+scaled) and the Q tile. 16 float4 per thread each.
    const float* ch = g_C + h * DD * DD;
    #pragma unroll
    for (int e = 0; e < 16; e++) {
        const int l4 = tid + 64 * e;
        const int i = l4 >> 4;
        const int c4 = l4 & 15;
        *(float4*)&Cs[i][c4 * 4] = *(const float4*)(ch + i * DD + c4 * 4);
        *(float4*)&Qs[i][c4 * 4] = *(const float4*)(qh + (size_t)i * SS + c4 * 4);
    }
    __syncthreads();

    // Column softmax numerator over d=64: each thread owns one s-column.
    {
        float sum = 0.f;
        #pragma unroll 8
        for (int i = 0; i < 64; i++) {
            const float ev = __expf(Qs[i][tid]);
            Qs[i][tid] = ev;
            sum += ev;
        }
        rs[tid] = 1.0f / sum;
    }
    __syncthreads();

    const int ts = tid & 7;   // s-group: cols 8*ts .. +7
    const int tj = tid >> 3;  // j-group: rows 8*tj .. +7

    unsigned long long acc[8][4];  // [j][s-pair]
    #pragma unroll
    for (int j = 0; j < 8; j++)
        #pragma unroll
        for (int m = 0; m < 4; m++) acc[j][m] = 0ull;

    #pragma unroll 8
    for (int i = 0; i < 64; i++) {
        unsigned long long a[4];
        #pragma unroll
        for (int m = 0; m < 4; m++)
            a[m] = *(const unsigned long long*)&Qs[i][8 * ts + 2 * m];
        #pragma unroll
        for (int j = 0; j < 8; j++) {
            const unsigned long long bb = dup2(Cs[i][8 * tj + j]);
            #pragma unroll
            for (int m = 0; m < 4; m++) fma2(acc[j][m], a[m], bb);
        }
    }

    // Epilogue: multiply by rinv[s], store 8 contiguous floats per output row.
    float rv[8];
    #pragma unroll
    for (int m = 0; m < 8; m++) rv[m] = rs[8 * ts + m];
    #pragma unroll
    for (int j = 0; j < 8; j++) {
        float o[8];
        #pragma unroll
        for (int m = 0; m < 4; m++) {
            const float2 f = unpack2(acc[j][m]);
            o[2 * m]     = f.x * rv[2 * m];
            o[2 * m + 1] = f.y * rv[2 * m + 1];
        }
        float* dst = oh + (size_t)(8 * tj + j) * SS + 8 * ts;
        *(float4*)(dst)     = make_float4(o[0], o[1], o[2], o[3]);
        *(float4*)(dst + 4) = make_float4(o[4], o[5], o[6], o[7]);
    }
}

extern "C" void kernel_launch(void* const* d_in, const int* in_sizes, int n_in,
                              void* d_out, int out_size) {
    const float* q = (const float*)d_in[0];
    const float* k = (const float*)d_in[1];
    const float* v = (const float*)d_in[2];
    float* out = (float*)d_out;

    dim3 gB(NC, NHEADS);
    kB<<<gB, 64>>>(k, v);
    kB2<<<(NHEADS * DD * DD + 255) / 256, 256>>>();
    dim3 gC(SS / 64, NHEADS);
    kC<<<gC, 64>>>(q, out);
}

// round 5
// speedup vs baseline: 1.0058x; 1.0058x over previous
#include <cuda_runtime.h>

// Problem constants: (b=4, n=8, d=64, s=8192) fp32
#define DD 64
#define SS 8192
#define NHEADS 32            // b * n_heads
#define NC 32                // split-K chunks over s for context GEMM
#define CHUNK (SS / NC)      // 256
#define TSZ 32               // s-tile inside a chunk
#define PADW 68              // smem row pad (16B-aligned rows, modest conflicts)

// Scratch (no allocations allowed)
__device__ float g_Upart[NHEADS * NC * DD * DD];  // 16.8 MB
__device__ float g_Zpart[NHEADS * NC * DD];
__device__ float g_C[NHEADS * DD * DD];           // C[i][j] * scale / Z_i

// ---- Blackwell packed fp32 pair math (2x FFMA rate; PTX-only) ----
__device__ __forceinline__ void fma2(unsigned long long &d, unsigned long long a, unsigned long long b) {
    asm("fma.rn.f32x2 %0, %1, %2, %0;" : "+l"(d) : "l"(a), "l"(b));
}
__device__ __forceinline__ unsigned long long dup2(float x) {
    unsigned long long r;
    asm("mov.b64 %0, {%1, %1};" : "=l"(r) : "f"(x));
    return r;
}
__device__ __forceinline__ float2 unpack2(unsigned long long v) {
    float2 f;
    asm("mov.b64 {%0, %1}, %2;" : "=f"(f.x), "=f"(f.y) : "l"(v));
    return f;
}

// ============================================================================
// Kernel B: per (head, chunk): U_part[i][j] = sum_s exp(k[i,s]) * v[j,s]
//                              Z_part[i]    = sum_s exp(k[i,s])
// 64 threads, each computes an 8x8 output tile (4 i-pairs x 8 j in f32x2).
// ============================================================================
__global__ __launch_bounds__(64) void kB(const float* __restrict__ K,
                                         const float* __restrict__ V) {
    __shared__ __align__(16) float Kt[TSZ][PADW];  // [s-in-tile][i] (exp applied)
    __shared__ __align__(16) float Vt[TSZ][PADW];  // [s-in-tile][j]

    const int h = blockIdx.y;
    const int c = blockIdx.x;
    const float* kh = K + (size_t)h * DD * SS + c * CHUNK;
    const float* vh = V + (size_t)h * DD * SS + c * CHUNK;

    const int tid = threadIdx.x;
    const int ti = tid & 7;     // i-group: rows 8*ti .. +7
    const int tj = tid >> 3;    // j-group: cols 8*tj .. +7
    const int lrow = tid >> 3;  // loader: base row
    const int lc4  = tid & 7;   // loader: float4 slot within 32-float tile row

    unsigned long long acc[4][8];  // [i-pair][j]
    #pragma unroll
    for (int m = 0; m < 4; m++)
        #pragma unroll
        for (int j = 0; j < 8; j++) acc[m][j] = 0ull;

    float zacc[8];
    #pragma unroll
    for (int e = 0; e < 8; e++) zacc[e] = 0.f;

    for (int tt = 0; tt < CHUNK / TSZ; ++tt) {
        const int s0 = tt * TSZ;
        __syncthreads();
        // Load + exp + transpose K, transpose V. 8 float4 per thread per array.
        #pragma unroll
        for (int e = 0; e < 8; ++e) {
            const int row = lrow + 8 * e;
            const float4 k4 = *(const float4*)(kh + (size_t)row * SS + s0 + lc4 * 4);
            const float e0 = __expf(k4.x), e1 = __expf(k4.y),
                        e2 = __expf(k4.z), e3 = __expf(k4.w);
            Kt[lc4 * 4 + 0][row] = e0;
            Kt[lc4 * 4 + 1][row] = e1;
            Kt[lc4 * 4 + 2][row] = e2;
            Kt[lc4 * 4 + 3][row] = e3;
            zacc[e] += (e0 + e1) + (e2 + e3);
            const float4 v4 = *(const float4*)(vh + (size_t)row * SS + s0 + lc4 * 4);
            Vt[lc4 * 4 + 0][row] = v4.x;
            Vt[lc4 * 4 + 1][row] = v4.y;
            Vt[lc4 * 4 + 2][row] = v4.z;
            Vt[lc4 * 4 + 3][row] = v4.w;
        }
        __syncthreads();
        // 64x64 x TSZ outer-product accumulation, packed pairs along i.
        // Vectorized smem reads: 2x LDS.128 per operand.
        #pragma unroll 4
        for (int t = 0; t < TSZ; ++t) {
            const ulonglong2 a01 = *(const ulonglong2*)&Kt[t][8 * ti];
            const ulonglong2 a23 = *(const ulonglong2*)&Kt[t][8 * ti + 4];
            unsigned long long a[4];
            a[0] = a01.x; a[1] = a01.y; a[2] = a23.x; a[3] = a23.y;
            const float4 b0 = *(const float4*)&Vt[t][8 * tj];
            const float4 b1 = *(const float4*)&Vt[t][8 * tj + 4];
            unsigned long long bb[8];
            bb[0] = dup2(b0.x); bb[1] = dup2(b0.y); bb[2] = dup2(b0.z); bb[3] = dup2(b0.w);
            bb[4] = dup2(b1.x); bb[5] = dup2(b1.y); bb[6] = dup2(b1.z); bb[7] = dup2(b1.w);
            #pragma unroll
            for (int j = 0; j < 8; j++) {
                #pragma unroll
                for (int m = 0; m < 4; m++) fma2(acc[m][j], a[m], bb[j]);
            }
        }
    }

    // Store partial U (no atomics; reduced by kB2).
    float* up = g_Upart + (size_t)(h * NC + c) * DD * DD;
    #pragma unroll
    for (int m = 0; m < 4; m++) {
        float r0[8], r1[8];
        #pragma unroll
        for (int j = 0; j < 8; j++) {
            const float2 f = unpack2(acc[m][j]);
            r0[j] = f.x;
            r1[j] = f.y;
        }
        const int i0 = 8 * ti + 2 * m;
        *(float4*)(up + i0 * DD + 8 * tj)           = make_float4(r0[0], r0[1], r0[2], r0[3]);
        *(float4*)(up + i0 * DD + 8 * tj + 4)       = make_float4(r0[4], r0[5], r0[6], r0[7]);
        *(float4*)(up + (i0 + 1) * DD + 8 * tj)     = make_float4(r1[0], r1[1], r1[2], r1[3]);
        *(float4*)(up + (i0 + 1) * DD + 8 * tj + 4) = make_float4(r1[4], r1[5], r1[6], r1[7]);
    }

    // Z partial: reduce across the 8 lanes sharing a row (lc4 = 0..7).
    #pragma unroll
    for (int e = 0; e < 8; e++) {
        float z = zacc[e];
        z += __shfl_down_sync(0xffffffffu, z, 4, 8);
        z += __shfl_down_sync(0xffffffffu, z, 2, 8);
        z += __shfl_down_sync(0xffffffffu, z, 1, 8);
        if (lc4 == 0) g_Zpart[(h * NC + c) * DD + lrow + 8 * e] = z;
    }
}

// ============================================================================
// Kernel B2: reduce NC partials -> g_C[i][j] = scale * U[i][j] / Z[i]
// ============================================================================
__global__ void kB2() {
    const int idx = blockIdx.x * 256 + threadIdx.x;
    if (idx >= NHEADS * DD * DD) return;
    const int h = idx >> 12;       // / 4096
    const int ij = idx & 4095;
    const int i = ij >> 6;
    float u = 0.f;
    #pragma unroll
    for (int c = 0; c < NC; c++) u += g_Upart[((size_t)(h * NC + c) << 12) + ij];
    float z = 0.f;
    #pragma unroll
    for (int c = 0; c < NC; c++) z += g_Zpart[(h * NC + c) * DD + i];
    g_C[idx] = u * (0.125f / z);   // scale = 64^-0.5 = 0.125
}

// ============================================================================
// Kernel C: per (head, 64-wide s-tile):
//   qe[i][s] = exp(q[i][s]); rinv[s] = 1/sum_i qe
//   out[j][s] = rinv[s] * sum_i g_C[i][j] * qe[i][s]
// 64 threads, 8j x 8s register tile (s-pairs packed for f32x2).
// ============================================================================
__global__ __launch_bounds__(64) void kC(const float* __restrict__ Q,
                                         float* __restrict__ O) {
    __shared__ __align__(16) float Cs[DD][PADW];
    __shared__ __align__(16) float Qs[DD][PADW];
    __shared__ float rs[64];

    const int h = blockIdx.y;
    const int s0 = blockIdx.x * 64;
    const float* qh = Q + (size_t)h * DD * SS + s0;
    float* oh = O + (size_t)h * DD * SS + s0;
    const int tid = threadIdx.x;

    // Load C (already normalized+scaled) and the Q tile. 16 float4 per thread each.
    const float* ch = g_C + h * DD * DD;
    #pragma unroll
    for (int e = 0; e < 16; e++) {
        const int l4 = tid + 64 * e;
        const int i = l4 >> 4;
        const int c4 = l4 & 15;
        *(float4*)&Cs[i][c4 * 4] = *(const float4*)(ch + i * DD + c4 * 4);
        *(float4*)&Qs[i][c4 * 4] = *(const float4*)(qh + (size_t)i * SS + c4 * 4);
    }
    __syncthreads();

    // Column softmax numerator over d=64: each thread owns one s-column.
    {
        float sum = 0.f;
        #pragma unroll 8
        for (int i = 0; i < 64; i++) {
            const float ev = __expf(Qs[i][tid]);
            Qs[i][tid] = ev;
            sum += ev;
        }
        rs[tid] = 1.0f / sum;
    }
    __syncthreads();

    const int ts = tid & 7;   // s-group: cols 8*ts .. +7
    const int tj = tid >> 3;  // j-group: rows 8*tj .. +7

    unsigned long long acc[8][4];  // [j][s-pair]
    #pragma unroll
    for (int j = 0; j < 8; j++)
        #pragma unroll
        for (int m = 0; m < 4; m++) acc[j][m] = 0ull;

    #pragma unroll 4
    for (int i = 0; i < 64; i++) {
        const ulonglong2 a01 = *(const ulonglong2*)&Qs[i][8 * ts];
        const ulonglong2 a23 = *(const ulonglong2*)&Qs[i][8 * ts + 4];
        unsigned long long a[4];
        a[0] = a01.x; a[1] = a01.y; a[2] = a23.x; a[3] = a23.y;
        const float4 b0 = *(const float4*)&Cs[i][8 * tj];
        const float4 b1 = *(const float4*)&Cs[i][8 * tj + 4];
        unsigned long long bb[8];
        bb[0] = dup2(b0.x); bb[1] = dup2(b0.y); bb[2] = dup2(b0.z); bb[3] = dup2(b0.w);
        bb[4] = dup2(b1.x); bb[5] = dup2(b1.y); bb[6] = dup2(b1.z); bb[7] = dup2(b1.w);
        #pragma unroll
        for (int j = 0; j < 8; j++) {
            #pragma unroll
            for (int m = 0; m < 4; m++) fma2(acc[j][m], a[m], bb[j]);
        }
    }

    // Epilogue: multiply by rinv[s], store 8 contiguous floats per output row.
    float rv[8];
    #pragma unroll
    for (int m = 0; m < 8; m++) rv[m] = rs[8 * ts + m];
    #pragma unroll
    for (int j = 0; j < 8; j++) {
        float o[8];
        #pragma unroll
        for (int m = 0; m < 4; m++) {
            const float2 f = unpack2(acc[j][m]);
            o[2 * m]     = f.x * rv[2 * m];
            o[2 * m + 1] = f.y * rv[2 * m + 1];
        }
        float* dst = oh + (size_t)(8 * tj + j) * SS + 8 * ts;
        *(float4*)(dst)     = make_float4(o[0], o[1], o[2], o[3]);
        *(float4*)(dst + 4) = make_float4(o[4], o[5], o[6], o[7]);
    }
}

extern "C" void kernel_launch(void* const* d_in, const int* in_sizes, int n_in,
                              void* d_out, int out_size) {
    const float* q = (const float*)d_in[0];
    const float* k = (const float*)d_in[1];
    const float* v = (const float*)d_in[2];
    float* out = (float*)d_out;

    dim3 gB(NC, NHEADS);
    kB<<<gB, 64>>>(k, v);
    kB2<<<(NHEADS * DD * DD + 255) / 256, 256>>>();
    dim3 gC(SS / 64, NHEADS);
    kC<<<gC, 64>>>(q, out);
}

// round 8
// speedup vs baseline: 1.5678x; 1.5587x over previous
#include <cuda_runtime.h>
#include <cuda_bf16.h>
#include <cstdint>

// Problem constants: (b=4, n=8, d=64, s=8192) fp32
#define DD 64
#define SS 8192
#define NHEADS 32

// kB config
#define NCB 32
#define CHUNKB (SS / NCB)     // 256
#define NSTAGE (CHUNKB / 64)  // 4
#define KB_STAGE 32768        // A(16KB) + B(16KB)
#define KB_SMEM (2 * KB_STAGE)

// kC config
#define SCT 128               // s-tile per block
#define KC_SMEM (16384 + 32768 + 512)

// Scratch
__device__ float g_Upart[NHEADS * NCB * DD * DD];
__device__ float g_Zpart[NHEADS * NCB * DD];
__device__ unsigned short g_Cthi[NHEADS * DD * DD];  // C^T hi, [h][j][i] bf16 bits
__device__ unsigned short g_Ctlo[NHEADS * DD * DD];  // C^T lo

// ============================ helpers ============================
__device__ __forceinline__ uint32_t smem_u32(const void* p) {
    uint32_t a;
    asm("{ .reg .u64 t; cvta.to.shared.u64 t, %1; cvt.u32.u64 %0, t; }" : "=r"(a) : "l"(p));
    return a;
}
// XOR swizzle: 16B chunk permute within 128B, keyed by row.
__device__ __forceinline__ uint32_t swz(uint32_t row, uint32_t sbyte, uint32_t pitch) {
    return row * pitch + (sbyte ^ ((row & 7u) << 4));
}
__device__ __forceinline__ void ldsm_x4(uint32_t& r0, uint32_t& r1, uint32_t& r2, uint32_t& r3, uint32_t a) {
    asm volatile("ldmatrix.sync.aligned.m8n8.x4.shared.b16 {%0,%1,%2,%3}, [%4];"
                 : "=r"(r0), "=r"(r1), "=r"(r2), "=r"(r3) : "r"(a));
}
__device__ __forceinline__ void ldsm_x2t(uint32_t& r0, uint32_t& r1, uint32_t a) {
    asm volatile("ldmatrix.sync.aligned.m8n8.x2.trans.shared.b16 {%0,%1}, [%2];"
                 : "=r"(r0), "=r"(r1) : "r"(a));
}
__device__ __forceinline__ void mma_bf16(float* d, const uint32_t* a, uint32_t b0, uint32_t b1) {
    asm volatile("mma.sync.aligned.m16n8k16.row.col.f32.bf16.bf16.f32 "
                 "{%0,%1,%2,%3}, {%4,%5,%6,%7}, {%8,%9}, {%0,%1,%2,%3};"
                 : "+f"(d[0]), "+f"(d[1]), "+f"(d[2]), "+f"(d[3])
                 : "r"(a[0]), "r"(a[1]), "r"(a[2]), "r"(a[3]), "r"(b0), "r"(b1));
}
__device__ __forceinline__ uint32_t cvt2(float hi, float lo) {  // pack {low:lo, high:hi}
    uint32_t r;
    asm("cvt.rn.bf16x2.f32 %0, %1, %2;" : "=r"(r) : "f"(hi), "f"(lo));
    return r;
}
// Split 4 fp32 into bf16 hi (trunc) row and lo row (row+64), swizzled 8B stores.
__device__ __forceinline__ void store_split(char* base, int row, int sbyte, uint32_t pitch,
                                            float a0, float a1, float a2, float a3) {
    uint32_t u0 = __float_as_uint(a0), u1 = __float_as_uint(a1);
    uint32_t u2 = __float_as_uint(a2), u3 = __float_as_uint(a3);
    uint32_t hp01 = __byte_perm(u0, u1, 0x7632);
    uint32_t hp23 = __byte_perm(u2, u3, 0x7632);
    float l0 = a0 - __uint_as_float(u0 & 0xFFFF0000u);
    float l1 = a1 - __uint_as_float(u1 & 0xFFFF0000u);
    float l2 = a2 - __uint_as_float(u2 & 0xFFFF0000u);
    float l3 = a3 - __uint_as_float(u3 & 0xFFFF0000u);
    uint32_t lp01 = cvt2(l1, l0);
    uint32_t lp23 = cvt2(l3, l2);
    *(uint2*)(base + swz(row, sbyte, pitch))      = make_uint2(hp01, hp23);
    *(uint2*)(base + swz(row + 64, sbyte, pitch)) = make_uint2(lp01, lp23);
}

// ============================================================================
// kB: per (h, c): U_part[64i][64j] = sum_s exp(k[i,s]) v[j,s]; Z_part[i].
// HMMA bf16 2-split. 256 thr / 8 warps; warp tile 16(i) x 32(j).
// ============================================================================
__global__ __launch_bounds__(256) void kB(const float* __restrict__ K,
                                          const float* __restrict__ V) {
    extern __shared__ __align__(1024) char dsm[];
    const int tid = threadIdx.x;
    const int w = tid >> 5, lane = tid & 31;
    const int h = blockIdx.y, c = blockIdx.x;
    const float* kh = K + (size_t)h * DD * SS + c * CHUNKB;
    const float* vh = V + (size_t)h * DD * SS + c * CHUNKB;

    const int mt = w & 3;    // i-tile (16 rows)
    const int nh = w >> 2;   // j-half (32 cols)

    float acc[4][4];         // [n-tile][frag]
    #pragma unroll
    for (int t = 0; t < 4; t++)
        #pragma unroll
        for (int e = 0; e < 4; e++) acc[t][e] = 0.f;
    float zacc[4] = {0.f, 0.f, 0.f, 0.f};

    for (int stage = 0; stage < NSTAGE; ++stage) {
        char* As = dsm + (stage & 1) * KB_STAGE;
        char* Bs = As + 16384;
        const int s0 = stage * 64;
        // convert: 64 rows x 64 s each of K and V
        #pragma unroll
        for (int e = 0; e < 4; ++e) {
            const int f = tid + 256 * e;
            const int row = f >> 4, c4 = f & 15;
            const float4 k4 = *(const float4*)(kh + (size_t)row * SS + s0 + 4 * c4);
            const float e0 = __expf(k4.x), e1 = __expf(k4.y),
                        e2 = __expf(k4.z), e3 = __expf(k4.w);
            zacc[e] += (e0 + e1) + (e2 + e3);
            store_split(As, row, 8 * c4, 128, e0, e1, e2, e3);
            const float4 v4 = *(const float4*)(vh + (size_t)row * SS + s0 + 4 * c4);
            store_split(Bs, row, 8 * c4, 128, v4.x, v4.y, v4.z, v4.w);
        }
        __syncthreads();
        const uint32_t Au = smem_u32(As), Bu = smem_u32(Bs);
        const uint32_t rA = 16 * mt + (lane & 15);
        const uint32_t rB = 32 * nh + (lane & 15);
        #pragma unroll
        for (int kk = 0; kk < 4; ++kk) {
            const uint32_t cb = 32 * kk + 16 * (lane >> 4);
            uint32_t ah[4], al[4];
            ldsm_x4(ah[0], ah[1], ah[2], ah[3], Au + swz(rA, cb, 128));
            ldsm_x4(al[0], al[1], al[2], al[3], Au + swz(rA + 64, cb, 128));
            uint32_t bh0[4], bh1[4], bl0[4], bl1[4];
            ldsm_x4(bh0[0], bh0[1], bh0[2], bh0[3], Bu + swz(rB, cb, 128));
            ldsm_x4(bh1[0], bh1[1], bh1[2], bh1[3], Bu + swz(rB + 16, cb, 128));
            ldsm_x4(bl0[0], bl0[1], bl0[2], bl0[3], Bu + swz(rB + 64, cb, 128));
            ldsm_x4(bl1[0], bl1[1], bl1[2], bl1[3], Bu + swz(rB + 80, cb, 128));
            // n-tiles 0,1 from bh0/bl0 (regs {sel, sel+2}); 2,3 from bh1/bl1
            #pragma unroll
            for (int t = 0; t < 4; ++t) {
                const uint32_t* bh = (t < 2) ? bh0 : bh1;
                const uint32_t* bl = (t < 2) ? bl0 : bl1;
                const int sel = t & 1;
                mma_bf16(acc[t], ah, bh[sel], bh[sel + 2]);   // hi*hi
                mma_bf16(acc[t], ah, bl[sel], bl[sel + 2]);   // hi*lo
                mma_bf16(acc[t], al, bh[sel], bh[sel + 2]);   // lo*hi
            }
        }
        __syncthreads();
    }

    // Z partials
    {
        float* zp = g_Zpart + (h * NCB + c) * DD;
        #pragma unroll
        for (int e = 0; e < 4; ++e) {
            float z = zacc[e];
            z += __shfl_down_sync(0xffffffffu, z, 8, 16);
            z += __shfl_down_sync(0xffffffffu, z, 4, 16);
            z += __shfl_down_sync(0xffffffffu, z, 2, 16);
            z += __shfl_down_sync(0xffffffffu, z, 1, 16);
            if ((tid & 15) == 0) zp[(tid >> 4) + 16 * e] = z;
        }
    }

    // acc -> g_Upart
    float* up = g_Upart + (size_t)(h * NCB + c) * DD * DD;
    const int i0 = 16 * mt + (lane >> 2);
    const int j0 = 32 * nh + 2 * (lane & 3);
    #pragma unroll
    for (int t = 0; t < 4; ++t) {
        *(float2*)(up + i0 * DD + j0 + 8 * t)       = make_float2(acc[t][0], acc[t][1]);
        *(float2*)(up + (i0 + 8) * DD + j0 + 8 * t) = make_float2(acc[t][2], acc[t][3]);
    }
}

// ============================================================================
// kB2: reduce partials -> C^T split bf16: g_Cthi/lo[h][j][i]
// ============================================================================
__global__ void kB2() {
    const int idx = blockIdx.x * 256 + threadIdx.x;
    if (idx >= NHEADS * DD * DD) return;
    const int h = idx >> 12;
    const int ij = idx & 4095;
    const int i = ij >> 6, j = ij & 63;
    float u = 0.f;
    #pragma unroll
    for (int c = 0; c < NCB; c++) u += g_Upart[((size_t)(h * NCB + c) << 12) + ij];
    float z = 0.f;
    #pragma unroll
    for (int c = 0; c < NCB; c++) z += g_Zpart[(h * NCB + c) * DD + i];
    const float cval = u * (0.125f / z);
    const uint32_t ub = __float_as_uint(cval);
    const float hi = __uint_as_float(ub & 0xFFFF0000u);
    const float lo = cval - hi;
    __nv_bfloat16 lb = __float2bfloat16(lo);
    g_Cthi[h * 4096 + j * 64 + i] = (unsigned short)(ub >> 16);
    g_Ctlo[h * 4096 + j * 64 + i] = *(unsigned short*)&lb;
}

// ============================================================================
// kC: per (h, s-tile 128): out[j][s] = rinv[s] * sum_i Ct[j][i] * exp(q[i][s])
// 128 thr / 4 warps; warp = (j-half 32) x (s-half 64). HMMA bf16 2-split.
// ============================================================================
__global__ __launch_bounds__(128) void kC(const float* __restrict__ Q,
                                          float* __restrict__ O) {
    extern __shared__ __align__(1024) char dsm[];
    char* Asm = dsm;               // Ct tile: [128 rows][128B]  (j rows, hi/lo)
    char* Bsm = dsm + 16384;       // qe tile: [128 rows][256B]  (i rows, hi/lo)
    float* rs = (float*)(dsm + 16384 + 32768);  // [128]

    const int tid = threadIdx.x;
    const int w = tid >> 5, lane = tid & 31;
    const int h = blockIdx.y;
    const int stile = blockIdx.x;
    const float* qh = Q + (size_t)h * DD * SS + stile * SCT;
    float* oh = O + (size_t)h * DD * SS + stile * SCT;

    // Load C^T hi/lo into swizzled smem (16KB, 8 uint4/thread)
    {
        const unsigned short* src_hi = g_Cthi + h * 4096;
        const unsigned short* src_lo = g_Ctlo + h * 4096;
        #pragma unroll
        for (int e = 0; e < 8; ++e) {
            const int u = tid + 128 * e;
            const int row = u >> 3, sb = (u & 7) * 16;
            const unsigned short* s = (row < 64) ? (src_hi + row * 64 + (u & 7) * 8)
                                                 : (src_lo + (row - 64) * 64 + (u & 7) * 8);
            *(uint4*)(Asm + swz(row, sb, 128)) = *(const uint4*)s;
        }
    }
    // Convert q tile: 64 i x 128 s -> exp -> hi/lo
    #pragma unroll
    for (int e = 0; e < 16; ++e) {
        const int f = tid + 128 * e;
        const int row = f >> 5, c4 = f & 31;
        const float4 q4 = *(const float4*)(qh + (size_t)row * SS + 4 * c4);
        store_split(Bsm, row, 8 * c4, 256,
                    __expf(q4.x), __expf(q4.y), __expf(q4.z), __expf(q4.w));
    }
    __syncthreads();

    // rinv per s column (thread = one s)
    {
        float sum = 0.f;
        #pragma unroll 8
        for (int i = 0; i < 64; ++i) {
            const __nv_bfloat16 bh = *(const __nv_bfloat16*)(Bsm + swz(i, 2 * tid, 256));
            const __nv_bfloat16 bl = *(const __nv_bfloat16*)(Bsm + swz(i + 64, 2 * tid, 256));
            sum += __bfloat162float(bh) + __bfloat162float(bl);
        }
        rs[tid] = 1.0f / sum;
    }
    __syncthreads();

    const int p = w & 1;    // j-half
    const int sh = w >> 1;  // s-half (64)
    const uint32_t Au = smem_u32(Asm), Bu = smem_u32(Bsm);

    // A fragments (reused across all s): [mt2][kk][hi/lo][4]
    uint32_t ah[2][4][4], al[2][4][4];
    #pragma unroll
    for (int mt2 = 0; mt2 < 2; ++mt2) {
        const uint32_t rA = 32 * p + 16 * mt2 + (lane & 15);
        #pragma unroll
        for (int kk = 0; kk < 4; ++kk) {
            const uint32_t cb = 32 * kk + 16 * (lane >> 4);
            ldsm_x4(ah[mt2][kk][0], ah[mt2][kk][1], ah[mt2][kk][2], ah[mt2][kk][3],
                    Au + swz(rA, cb, 128));
            ldsm_x4(al[mt2][kk][0], al[mt2][kk][1], al[mt2][kk][2], al[mt2][kk][3],
                    Au + swz(rA + 64, cb, 128));
        }
    }

    float acc[2][8][4];
    #pragma unroll
    for (int m = 0; m < 2; m++)
        #pragma unroll
        for (int t = 0; t < 8; t++)
            #pragma unroll
            for (int e = 0; e < 4; e++) acc[m][t][e] = 0.f;

    const uint32_t rBl = (lane & 7) + 8 * ((lane >> 3) & 1);  // i row within k16
    #pragma unroll
    for (int nt = 0; nt < 8; ++nt) {
        const uint32_t sb = 2 * (64 * sh + 8 * nt);  // byte offset of 8-s group
        #pragma unroll
        for (int kk = 0; kk < 4; ++kk) {
            uint32_t bh0, bh1, bl0, bl1;
            ldsm_x2t(bh0, bh1, Bu + swz(16 * kk + rBl, sb, 256));
            ldsm_x2t(bl0, bl1, Bu + swz(16 * kk + rBl + 64, sb, 256));
            #pragma unroll
            for (int mt2 = 0; mt2 < 2; ++mt2) {
                mma_bf16(acc[mt2][nt], ah[mt2][kk], bh0, bh1);
                mma_bf16(acc[mt2][nt], ah[mt2][kk], bl0, bl1);
                mma_bf16(acc[mt2][nt], al[mt2][kk], bh0, bh1);
            }
        }
    }

    // Epilogue: scale by rinv and store
    #pragma unroll
    for (int mt2 = 0; mt2 < 2; ++mt2) {
        const int j0 = 32 * p + 16 * mt2 + (lane >> 2);
        #pragma unroll
        for (int nt = 0; nt < 8; ++nt) {
            const int sl = 64 * sh + 8 * nt + 2 * (lane & 3);
            const float r0 = rs[sl], r1 = rs[sl + 1];
            *(float2*)(oh + (size_t)j0 * SS + sl) =
                make_float2(acc[mt2][nt][0] * r0, acc[mt2][nt][1] * r1);
            *(float2*)(oh + (size_t)(j0 + 8) * SS + sl) =
                make_float2(acc[mt2][nt][2] * r0, acc[mt2][nt][3] * r1);
        }
    }
}

extern "C" void kernel_launch(void* const* d_in, const int* in_sizes, int n_in,
                              void* d_out, int out_size) {
    const float* q = (const float*)d_in[0];
    const float* k = (const float*)d_in[1];
    const float* v = (const float*)d_in[2];
    float* out = (float*)d_out;

    cudaFuncSetAttribute(kB, cudaFuncAttributeMaxDynamicSharedMemorySize, KB_SMEM);
    cudaFuncSetAttribute(kC, cudaFuncAttributeMaxDynamicSharedMemorySize, KC_SMEM);

    dim3 gB(NCB, NHEADS);
    kB<<<gB, 256, KB_SMEM>>>(k, v);
    kB2<<<(NHEADS * DD * DD + 255) / 256, 256>>>();
    dim3 gC(SS / SCT, NHEADS);
    kC<<<gC, 128, KC_SMEM>>>(q, out);
}

// round 10
// speedup vs baseline: 1.6513x; 1.0533x over previous
#include <cuda_runtime.h>
#include <cuda_bf16.h>
#include <cstdint>

// Problem constants: (b=4, n=8, d=64, s=8192) fp32
#define DD 64
#define SS 8192
#define NHEADS 32

// kB config
#define NCB 32
#define CHUNKB (SS / NCB)     // 256
#define NSTAGE (CHUNKB / 64)  // 4
#define KB_SMEM 32768         // single buffer: A(16KB) + B(16KB)

// kC config
#define SCT 64                // s-tile per block
#define KC_SMEM (16384 + 16384 + 256)

// Scratch
__device__ float g_Upart[NHEADS * NCB * DD * DD];
__device__ float g_Zpart[NHEADS * NCB * DD];
__device__ unsigned short g_Cthi[NHEADS * DD * DD];  // C^T hi, [h][j][i] bf16 bits
__device__ unsigned short g_Ctlo[NHEADS * DD * DD];  // C^T lo

// ============================ helpers ============================
__device__ __forceinline__ uint32_t smem_u32(const void* p) {
    uint32_t a;
    asm("{ .reg .u64 t; cvta.to.shared.u64 t, %1; cvt.u32.u64 %0, t; }" : "=r"(a) : "l"(p));
    return a;
}
// XOR swizzle: 16B chunk permute within 128B, keyed by row.
__device__ __forceinline__ uint32_t swz(uint32_t row, uint32_t sbyte, uint32_t pitch) {
    return row * pitch + (sbyte ^ ((row & 7u) << 4));
}
__device__ __forceinline__ void ldsm_x4(uint32_t& r0, uint32_t& r1, uint32_t& r2, uint32_t& r3, uint32_t a) {
    asm volatile("ldmatrix.sync.aligned.m8n8.x4.shared.b16 {%0,%1,%2,%3}, [%4];"
                 : "=r"(r0), "=r"(r1), "=r"(r2), "=r"(r3) : "r"(a));
}
__device__ __forceinline__ void ldsm_x2t(uint32_t& r0, uint32_t& r1, uint32_t a) {
    asm volatile("ldmatrix.sync.aligned.m8n8.x2.trans.shared.b16 {%0,%1}, [%2];"
                 : "=r"(r0), "=r"(r1) : "r"(a));
}
__device__ __forceinline__ void mma_bf16(float* d, const uint32_t* a, uint32_t b0, uint32_t b1) {
    asm volatile("mma.sync.aligned.m16n8k16.row.col.f32.bf16.bf16.f32 "
                 "{%0,%1,%2,%3}, {%4,%5,%6,%7}, {%8,%9}, {%0,%1,%2,%3};"
                 : "+f"(d[0]), "+f"(d[1]), "+f"(d[2]), "+f"(d[3])
                 : "r"(a[0]), "r"(a[1]), "r"(a[2]), "r"(a[3]), "r"(b0), "r"(b1));
}
__device__ __forceinline__ uint32_t cvt2(float hi, float lo) {  // pack {low:lo, high:hi}
    uint32_t r;
    asm("cvt.rn.bf16x2.f32 %0, %1, %2;" : "=r"(r) : "f"(hi), "f"(lo));
    return r;
}
// Split 4 fp32 into bf16 hi (trunc) row and lo row (row+64), swizzled 8B stores.
__device__ __forceinline__ void store_split(char* base, int row, int sbyte, uint32_t pitch,
                                            float a0, float a1, float a2, float a3) {
    uint32_t u0 = __float_as_uint(a0), u1 = __float_as_uint(a1);
    uint32_t u2 = __float_as_uint(a2), u3 = __float_as_uint(a3);
    uint32_t hp01 = __byte_perm(u0, u1, 0x7632);
    uint32_t hp23 = __byte_perm(u2, u3, 0x7632);
    float l0 = a0 - __uint_as_float(u0 & 0xFFFF0000u);
    float l1 = a1 - __uint_as_float(u1 & 0xFFFF0000u);
    float l2 = a2 - __uint_as_float(u2 & 0xFFFF0000u);
    float l3 = a3 - __uint_as_float(u3 & 0xFFFF0000u);
    uint32_t lp01 = cvt2(l1, l0);
    uint32_t lp23 = cvt2(l3, l2);
    *(uint2*)(base + swz(row, sbyte, pitch))      = make_uint2(hp01, hp23);
    *(uint2*)(base + swz(row + 64, sbyte, pitch)) = make_uint2(lp01, lp23);
}

// ============================================================================
// kB: per (h, c): U_part[64i][64j] = sum_s exp(k[i,s]) v[j,s]; Z_part[i].
// HMMA bf16 2-split. 256 thr / 8 warps; warp tile 16(i) x 32(j).
// Single smem buffer (32KB) -> 4 blocks/SM (RF-bound), occ 50%.
// ============================================================================
__global__ __launch_bounds__(256) void kB(const float* __restrict__ K,
                                          const float* __restrict__ V) {
    extern __shared__ __align__(1024) char dsm[];
    const int tid = threadIdx.x;
    const int w = tid >> 5, lane = tid & 31;
    const int h = blockIdx.y, c = blockIdx.x;
    const float* kh = K + (size_t)h * DD * SS + c * CHUNKB;
    const float* vh = V + (size_t)h * DD * SS + c * CHUNKB;

    const int mt = w & 3;    // i-tile (16 rows)
    const int nh = w >> 2;   // j-half (32 cols)

    float acc[4][4];         // [n-tile][frag]
    #pragma unroll
    for (int t = 0; t < 4; t++)
        #pragma unroll
        for (int e = 0; e < 4; e++) acc[t][e] = 0.f;
    float zacc[4] = {0.f, 0.f, 0.f, 0.f};

    char* As = dsm;
    char* Bs = dsm + 16384;
    const uint32_t Au = smem_u32(As), Bu = smem_u32(Bs);
    const uint32_t rA = 16 * mt + (lane & 15);
    const uint32_t rB = 32 * nh + (lane & 15);

    for (int stage = 0; stage < NSTAGE; ++stage) {
        const int s0 = stage * 64;
        if (stage > 0) __syncthreads();  // prior MMA readers done with buffer
        // convert: 64 rows x 64 s each of K and V
        #pragma unroll
        for (int e = 0; e < 4; ++e) {
            const int f = tid + 256 * e;
            const int row = f >> 4, c4 = f & 15;
            const float4 k4 = *(const float4*)(kh + (size_t)row * SS + s0 + 4 * c4);
            const float e0 = __expf(k4.x), e1 = __expf(k4.y),
                        e2 = __expf(k4.z), e3 = __expf(k4.w);
            zacc[e] += (e0 + e1) + (e2 + e3);
            store_split(As, row, 8 * c4, 128, e0, e1, e2, e3);
            const float4 v4 = *(const float4*)(vh + (size_t)row * SS + s0 + 4 * c4);
            store_split(Bs, row, 8 * c4, 128, v4.x, v4.y, v4.z, v4.w);
        }
        __syncthreads();
        #pragma unroll
        for (int kk = 0; kk < 4; ++kk) {
            const uint32_t cb = 32 * kk + 16 * (lane >> 4);
            uint32_t ah[4], al[4];
            ldsm_x4(ah[0], ah[1], ah[2], ah[3], Au + swz(rA, cb, 128));
            ldsm_x4(al[0], al[1], al[2], al[3], Au + swz(rA + 64, cb, 128));
            uint32_t bh0[4], bh1[4], bl0[4], bl1[4];
            ldsm_x4(bh0[0], bh0[1], bh0[2], bh0[3], Bu + swz(rB, cb, 128));
            ldsm_x4(bh1[0], bh1[1], bh1[2], bh1[3], Bu + swz(rB + 16, cb, 128));
            ldsm_x4(bl0[0], bl0[1], bl0[2], bl0[3], Bu + swz(rB + 64, cb, 128));
            ldsm_x4(bl1[0], bl1[1], bl1[2], bl1[3], Bu + swz(rB + 80, cb, 128));
            #pragma unroll
            for (int t = 0; t < 4; ++t) {
                const uint32_t* bh = (t < 2) ? bh0 : bh1;
                const uint32_t* bl = (t < 2) ? bl0 : bl1;
                const int sel = t & 1;
                mma_bf16(acc[t], ah, bh[sel], bh[sel + 2]);   // hi*hi
                mma_bf16(acc[t], ah, bl[sel], bl[sel + 2]);   // hi*lo
                mma_bf16(acc[t], al, bh[sel], bh[sel + 2]);   // lo*hi
            }
        }
    }

    // Z partials
    {
        float* zp = g_Zpart + (h * NCB + c) * DD;
        #pragma unroll
        for (int e = 0; e < 4; ++e) {
            float z = zacc[e];
            z += __shfl_down_sync(0xffffffffu, z, 8, 16);
            z += __shfl_down_sync(0xffffffffu, z, 4, 16);
            z += __shfl_down_sync(0xffffffffu, z, 2, 16);
            z += __shfl_down_sync(0xffffffffu, z, 1, 16);
            if ((tid & 15) == 0) zp[(tid >> 4) + 16 * e] = z;
        }
    }

    // acc -> g_Upart
    float* up = g_Upart + (size_t)(h * NCB + c) * DD * DD;
    const int i0 = 16 * mt + (lane >> 2);
    const int j0 = 32 * nh + 2 * (lane & 3);
    #pragma unroll
    for (int t = 0; t < 4; ++t) {
        *(float2*)(up + i0 * DD + j0 + 8 * t)       = make_float2(acc[t][0], acc[t][1]);
        *(float2*)(up + (i0 + 8) * DD + j0 + 8 * t) = make_float2(acc[t][2], acc[t][3]);
    }
}

// ============================================================================
// kB2: reduce partials -> C^T split bf16: g_Cthi/lo[h][j][i]
// ============================================================================
__global__ void kB2() {
    const int idx = blockIdx.x * 256 + threadIdx.x;
    if (idx >= NHEADS * DD * DD) return;
    const int h = idx >> 12;
    const int ij = idx & 4095;
    const int i = ij >> 6, j = ij & 63;
    float u = 0.f;
    #pragma unroll
    for (int c = 0; c < NCB; c++) u += g_Upart[((size_t)(h * NCB + c) << 12) + ij];
    float z = 0.f;
    #pragma unroll
    for (int c = 0; c < NCB; c++) z += g_Zpart[(h * NCB + c) * DD + i];
    const float cval = u * (0.125f / z);
    const uint32_t ub = __float_as_uint(cval);
    const float hi = __uint_as_float(ub & 0xFFFF0000u);
    const float lo = cval - hi;
    __nv_bfloat16 lb = __float2bfloat16(lo);
    g_Cthi[h * 4096 + j * 64 + i] = (unsigned short)(ub >> 16);
    g_Ctlo[h * 4096 + j * 64 + i] = *(unsigned short*)&lb;
}

// ============================================================================
// kC: per (h, s-tile 64): out[j][s] = rinv[s] * sum_i Ct[j][i] * exp(q[i][s])
// 128 thr / 4 warps; warp owns 16 j-rows x all 64 s. HMMA bf16 2-split.
// ============================================================================
__global__ __launch_bounds__(128) void kC(const float* __restrict__ Q,
                                          float* __restrict__ O) {
    extern __shared__ __align__(1024) char dsm[];
    char* Asm = dsm;               // Ct tile: [128 rows][128B] (j rows hi/lo, 64 i cols)
    char* Bsm = dsm + 16384;       // qe tile: [128 rows][128B] (i rows hi/lo, 64 s cols)
    float* rs = (float*)(dsm + 32768);  // [64]

    const int tid = threadIdx.x;
    const int w = tid >> 5, lane = tid & 31;
    const int h = blockIdx.y;
    const int stile = blockIdx.x;
    const float* qh = Q + (size_t)h * DD * SS + stile * SCT;
    float* oh = O + (size_t)h * DD * SS + stile * SCT;

    // Load C^T hi/lo into swizzled smem (16KB, 8 uint4/thread)
    {
        const unsigned short* src_hi = g_Cthi + h * 4096;
        const unsigned short* src_lo = g_Ctlo + h * 4096;
        #pragma unroll
        for (int e = 0; e < 8; ++e) {
            const int u = tid + 128 * e;
            const int row = u >> 3, sb = (u & 7) * 16;
            const unsigned short* s = (row < 64) ? (src_hi + row * 64 + (u & 7) * 8)
                                                 : (src_lo + (row - 64) * 64 + (u & 7) * 8);
            *(uint4*)(Asm + swz(row, sb, 128)) = *(const uint4*)s;
        }
    }
    // Convert q tile: 64 i x 64 s -> exp -> hi/lo. 8 float4/thread.
    #pragma unroll
    for (int e = 0; e < 8; ++e) {
        const int f = tid + 128 * e;
        const int row = f >> 4, c4 = f & 15;
        const float4 q4 = *(const float4*)(qh + (size_t)row * SS + 4 * c4);
        store_split(Bsm, row, 8 * c4, 128,
                    __expf(q4.x), __expf(q4.y), __expf(q4.z), __expf(q4.w));
    }
    __syncthreads();

    // rinv per s column (threads 0..63 own one s each)
    if (tid < 64) {
        float sum = 0.f;
        #pragma unroll 8
        for (int i = 0; i < 64; ++i) {
            const __nv_bfloat16 bh = *(const __nv_bfloat16*)(Bsm + swz(i, 2 * tid, 128));
            const __nv_bfloat16 bl = *(const __nv_bfloat16*)(Bsm + swz(i + 64, 2 * tid, 128));
            sum += __bfloat162float(bh) + __bfloat162float(bl);
        }
        rs[tid] = 1.0f / sum;
    }
    __syncthreads();

    const uint32_t Au = smem_u32(Asm), Bu = smem_u32(Bsm);

    // A fragments (warp's 16 j-rows, hi & lo), reused across all 8 n-tiles.
    uint32_t ah[4][4], al[4][4];
    {
        const uint32_t rA = 16 * w + (lane & 15);
        #pragma unroll
        for (int kk = 0; kk < 4; ++kk) {
            const uint32_t cb = 32 * kk + 16 * (lane >> 4);
            ldsm_x4(ah[kk][0], ah[kk][1], ah[kk][2], ah[kk][3], Au + swz(rA, cb, 128));
            ldsm_x4(al[kk][0], al[kk][1], al[kk][2], al[kk][3], Au + swz(rA + 64, cb, 128));
        }
    }

    float acc[8][4];
    #pragma unroll
    for (int t = 0; t < 8; t++)
        #pragma unroll
        for (int e = 0; e < 4; e++) acc[t][e] = 0.f;

    const uint32_t rBl = (lane & 7) + 8 * ((lane >> 3) & 1);  // i row within k16
    #pragma unroll
    for (int nt = 0; nt < 8; ++nt) {
        const uint32_t sb = 2 * (8 * nt);  // byte offset of 8-s group
        #pragma unroll
        for (int kk = 0; kk < 4; ++kk) {
            uint32_t bh0, bh1, bl0, bl1;
            ldsm_x2t(bh0, bh1, Bu + swz(16 * kk + rBl, sb, 128));
            ldsm_x2t(bl0, bl1, Bu + swz(16 * kk + rBl + 64, sb, 128));
            mma_bf16(acc[nt], ah[kk], bh0, bh1);   // hi*hi
            mma_bf16(acc[nt], ah[kk], bl0, bl1);   // hi*lo
            mma_bf16(acc[nt], al[kk], bh0, bh1);   // lo*hi
        }
    }

    // Epilogue: scale by rinv and store
    const int j0 = 16 * w + (lane >> 2);
    #pragma unroll
    for (int nt = 0; nt < 8; ++nt) {
        const int sl = 8 * nt + 2 * (lane & 3);
        const float r0 = rs[sl], r1 = rs[sl + 1];
        *(float2*)(oh + (size_t)j0 * SS + sl) =
            make_float2(acc[nt][0] * r0, acc[nt][1] * r1);
        *(float2*)(oh + (size_t)(j0 + 8) * SS + sl) =
            make_float2(acc[nt][2] * r0, acc[nt][3] * r1);
    }
}

extern "C" void kernel_launch(void* const* d_in, const int* in_sizes, int n_in,
                              void* d_out, int out_size) {
    const float* q = (const float*)d_in[0];
    const float* k = (const float*)d_in[1];
    const float* v = (const float*)d_in[2];
    float* out = (float*)d_out;

    cudaFuncSetAttribute(kB, cudaFuncAttributeMaxDynamicSharedMemorySize, KB_SMEM);
    cudaFuncSetAttribute(kC, cudaFuncAttributeMaxDynamicSharedMemorySize, KC_SMEM);

    dim3 gB(NCB, NHEADS);
    kB<<<gB, 256, KB_SMEM>>>(k, v);
    kB2<<<(NHEADS * DD * DD + 255) / 256, 256>>>();
    dim3 gC(SS / SCT, NHEADS);
    kC<<<gC, 128, KC_SMEM>>>(q, out);
}